// round 1
// baseline (speedup 1.0000x reference)
#include <cuda_runtime.h>

// Y: [16384, 2048] fp32, row-major.
// loss = sum_d | 1 - (sum_n Y[n,d]^2) / n |

#define N_ROWS   16384
#define N_COLS   2048
#define COLS4    (N_COLS / 4)        // 512 float4 per row
#define ROWS_PER_BLOCK 16
#define GRID1    (N_ROWS / ROWS_PER_BLOCK)   // 1024 blocks

// Scratch: per-block partial column sums of squares. 1024 * 2048 floats = 8 MB.
__device__ float4 g_partial[GRID1 * COLS4];

__global__ __launch_bounds__(COLS4) void colsq_kernel(
    const float4* __restrict__ Y, float* __restrict__ out)
{
    const int col4 = threadIdx.x;                       // 0..511
    const long base = (long)blockIdx.x * ROWS_PER_BLOCK * COLS4 + col4;

    float ax = 0.f, ay = 0.f, az = 0.f, aw = 0.f;
    #pragma unroll
    for (int r = 0; r < ROWS_PER_BLOCK; r++) {
        float4 v = Y[base + (long)r * COLS4];
        ax = fmaf(v.x, v.x, ax);
        ay = fmaf(v.y, v.y, ay);
        az = fmaf(v.z, v.z, az);
        aw = fmaf(v.w, v.w, aw);
    }
    float4 acc; acc.x = ax; acc.y = ay; acc.z = az; acc.w = aw;
    g_partial[(long)blockIdx.x * COLS4 + col4] = acc;

    // Zero the scalar output once; kernel2 runs after this kernel completes
    // (same stream), so ordering is guaranteed.
    if (blockIdx.x == 0 && threadIdx.x == 0) out[0] = 0.0f;
}

__global__ __launch_bounds__(1024) void reduce_kernel(float* __restrict__ out)
{
    // 2 blocks x 1024 threads: one thread per column.
    const int col = blockIdx.x * 1024 + threadIdx.x;    // 0..2047
    const int c4  = col >> 2;
    const int cl  = col & 3;

    const float* p = reinterpret_cast<const float*>(g_partial);
    // g_partial laid out as [GRID1][N_COLS] floats; column stride = N_COLS.
    float s0 = 0.f, s1 = 0.f, s2 = 0.f, s3 = 0.f;
    const long colOff = (long)c4 * 4 + cl;              // == col
    #pragma unroll 4
    for (int b = 0; b < GRID1; b += 4) {
        s0 += p[(long)(b + 0) * N_COLS + colOff];
        s1 += p[(long)(b + 1) * N_COLS + colOff];
        s2 += p[(long)(b + 2) * N_COLS + colOff];
        s3 += p[(long)(b + 3) * N_COLS + colOff];
    }
    float s = (s0 + s1) + (s2 + s3);

    float v = fabsf(1.0f - s * (1.0f / (float)N_ROWS));

    // Block reduction: 32 warps -> 1 value.
    __shared__ float red[32];
    #pragma unroll
    for (int o = 16; o > 0; o >>= 1)
        v += __shfl_down_sync(0xffffffff, v, o);
    if ((threadIdx.x & 31) == 0) red[threadIdx.x >> 5] = v;
    __syncthreads();
    if (threadIdx.x < 32) {
        float t = red[threadIdx.x];
        #pragma unroll
        for (int o = 16; o > 0; o >>= 1)
            t += __shfl_down_sync(0xffffffff, t, o);
        if (threadIdx.x == 0) atomicAdd(out, t);
    }
}

extern "C" void kernel_launch(void* const* d_in, const int* in_sizes, int n_in,
                              void* d_out, int out_size)
{
    const float4* Y = (const float4*)d_in[0];
    float* out = (float*)d_out;

    colsq_kernel<<<GRID1, COLS4>>>(Y, out);
    reduce_kernel<<<2, 1024>>>(out);
}

// round 2
// speedup vs baseline: 1.8421x; 1.8421x over previous
#include <cuda_runtime.h>

// Y: [16384, 2048] fp32, row-major.
// loss = sum_d | 1 - (sum_n Y[n,d]^2) / n |

#define N_ROWS   16384
#define N_COLS   2048
#define COLS4    (N_COLS / 4)        // 512 float4 per row
#define ROWS_PER_BLOCK 16
#define GRID1    (N_ROWS / ROWS_PER_BLOCK)   // 1024 blocks

// Scratch: per-block partial column sums of squares, [GRID1][COLS4] float4 = 8 MB.
__device__ float4 g_partial[GRID1 * COLS4];

__global__ __launch_bounds__(COLS4) void colsq_kernel(
    const float4* __restrict__ Y, float* __restrict__ out)
{
    const int col4 = threadIdx.x;                       // 0..511
    const long base = (long)blockIdx.x * ROWS_PER_BLOCK * COLS4 + col4;

    float ax = 0.f, ay = 0.f, az = 0.f, aw = 0.f;
    #pragma unroll
    for (int r = 0; r < ROWS_PER_BLOCK; r++) {
        float4 v = Y[base + (long)r * COLS4];
        ax = fmaf(v.x, v.x, ax);
        ay = fmaf(v.y, v.y, ay);
        az = fmaf(v.z, v.z, az);
        aw = fmaf(v.w, v.w, aw);
    }
    float4 acc; acc.x = ax; acc.y = ay; acc.z = az; acc.w = aw;
    g_partial[(long)blockIdx.x * COLS4 + col4] = acc;

    // Zero the scalar output; K2 (same stream, after K1) atomically adds into it.
    if (blockIdx.x == 0 && threadIdx.x == 0) out[0] = 0.0f;
}

// K2: 64 blocks x 1024 threads. Block b reduces f4-columns [b*8, b*8+8)
// over all 1024 K1 partials (8 MB, L2-hot). Coalesced: within a warp the 8
// adjacent f4-columns form one 128B line.
__global__ __launch_bounds__(1024) void reduce_kernel(float* __restrict__ out)
{
    const int t  = threadIdx.x;
    const int fc = t & 7;            // f4-column within block's set (0..7)
    const int rg = t >> 3;           // row-group (0..127)
    const int f4col = blockIdx.x * 8 + fc;   // 0..511

    const float4* __restrict__ p = g_partial;

    float4 a = make_float4(0.f, 0.f, 0.f, 0.f);
    #pragma unroll
    for (int i = 0; i < 8; i++) {
        const int row = rg + 128 * i;        // 0..1023
        float4 v = p[(long)row * COLS4 + f4col];
        a.x += v.x; a.y += v.y; a.z += v.z; a.w += v.w;
    }

    __shared__ float4 s[1024];               // [rg][fc] layout: index rg*8+fc == t
    s[t] = a;
    __syncthreads();

    // Tree-reduce over rg (128 -> 1) per fc.
    #pragma unroll
    for (int stride = 64; stride >= 1; stride >>= 1) {
        if (rg < stride) {
            float4 b2 = s[(rg + stride) * 8 + fc];
            float4 a2 = s[t];
            a2.x += b2.x; a2.y += b2.y; a2.z += b2.z; a2.w += b2.w;
            s[t] = a2;
        }
        __syncthreads();
    }

    // s[fc], fc in [0,8): column sums for this block's 32 scalar columns.
    if (t == 0) {
        const float inv_n = 1.0f / (float)N_ROWS;
        float total = 0.f;
        #pragma unroll
        for (int f = 0; f < 8; f++) {
            float4 d = s[f];
            total += fabsf(1.0f - d.x * inv_n);
            total += fabsf(1.0f - d.y * inv_n);
            total += fabsf(1.0f - d.z * inv_n);
            total += fabsf(1.0f - d.w * inv_n);
        }
        atomicAdd(out, total);
    }
}

extern "C" void kernel_launch(void* const* d_in, const int* in_sizes, int n_in,
                              void* d_out, int out_size)
{
    const float4* Y = (const float4*)d_in[0];
    float* out = (float*)d_out;

    colsq_kernel<<<GRID1, COLS4>>>(Y, out);
    reduce_kernel<<<64, 1024>>>(out);
}

// round 3
// speedup vs baseline: 1.8919x; 1.0270x over previous
#include <cuda_runtime.h>

// Y: [16384, 2048] fp32, row-major.
// loss = sum_d | 1 - (sum_n Y[n,d]^2) / n |

#define N_ROWS   16384
#define N_COLS   2048
#define COLS4    (N_COLS / 4)        // 512 float4 per row
#define ROWS_PER_BLOCK 64
#define GRID1    (N_ROWS / ROWS_PER_BLOCK)   // 256 blocks

// Scratch: per-block partial column sums of squares, [GRID1][COLS4] float4 = 2 MB.
__device__ float4 g_partial[GRID1 * COLS4];

__global__ __launch_bounds__(COLS4) void colsq_kernel(
    const float4* __restrict__ Y, float* __restrict__ out)
{
    const int col4 = threadIdx.x;                       // 0..511
    const long base = (long)blockIdx.x * ROWS_PER_BLOCK * COLS4 + col4;

    float ax = 0.f, ay = 0.f, az = 0.f, aw = 0.f;
    #pragma unroll
    for (int r = 0; r < ROWS_PER_BLOCK; r += 4) {
        float4 v0 = Y[base + (long)(r + 0) * COLS4];
        float4 v1 = Y[base + (long)(r + 1) * COLS4];
        float4 v2 = Y[base + (long)(r + 2) * COLS4];
        float4 v3 = Y[base + (long)(r + 3) * COLS4];
        ax = fmaf(v0.x, v0.x, ax); ay = fmaf(v0.y, v0.y, ay);
        az = fmaf(v0.z, v0.z, az); aw = fmaf(v0.w, v0.w, aw);
        ax = fmaf(v1.x, v1.x, ax); ay = fmaf(v1.y, v1.y, ay);
        az = fmaf(v1.z, v1.z, az); aw = fmaf(v1.w, v1.w, aw);
        ax = fmaf(v2.x, v2.x, ax); ay = fmaf(v2.y, v2.y, ay);
        az = fmaf(v2.z, v2.z, az); aw = fmaf(v2.w, v2.w, aw);
        ax = fmaf(v3.x, v3.x, ax); ay = fmaf(v3.y, v3.y, ay);
        az = fmaf(v3.z, v3.z, az); aw = fmaf(v3.w, v3.w, aw);
    }
    float4 acc; acc.x = ax; acc.y = ay; acc.z = az; acc.w = aw;
    g_partial[(long)blockIdx.x * COLS4 + col4] = acc;

    // Zero the scalar output; K2 (same stream, after K1) atomically adds into it.
    if (blockIdx.x == 0 && threadIdx.x == 0) out[0] = 0.0f;
}

// K2: 64 blocks x 1024 threads. Block b reduces f4-columns [b*8, b*8+8)
// over all 256 K1 partials (2 MB, L2-hot). Coalesced: within a warp the 8
// adjacent f4-columns form one 128B line.
__global__ __launch_bounds__(1024) void reduce_kernel(float* __restrict__ out)
{
    const int t  = threadIdx.x;
    const int fc = t & 7;            // f4-column within block's set (0..7)
    const int rg = t >> 3;           // row-group (0..127)
    const int f4col = blockIdx.x * 8 + fc;   // 0..511

    const float4* __restrict__ p = g_partial;

    float4 v0 = p[(long)rg * COLS4 + f4col];
    float4 v1 = p[(long)(rg + 128) * COLS4 + f4col];
    float4 a;
    a.x = v0.x + v1.x; a.y = v0.y + v1.y;
    a.z = v0.z + v1.z; a.w = v0.w + v1.w;

    __shared__ float4 s[1024];               // [rg][fc] layout: index rg*8+fc == t
    s[t] = a;
    __syncthreads();

    // Tree-reduce over rg (128 -> 1) per fc.
    #pragma unroll
    for (int stride = 64; stride >= 1; stride >>= 1) {
        if (rg < stride) {
            float4 b2 = s[(rg + stride) * 8 + fc];
            float4 a2 = s[t];
            a2.x += b2.x; a2.y += b2.y; a2.z += b2.z; a2.w += b2.w;
            s[t] = a2;
        }
        __syncthreads();
    }

    // s[fc], fc in [0,8): column sums for this block's 32 scalar columns.
    if (t == 0) {
        const float inv_n = 1.0f / (float)N_ROWS;
        float total = 0.f;
        #pragma unroll
        for (int f = 0; f < 8; f++) {
            float4 d = s[f];
            total += fabsf(1.0f - d.x * inv_n);
            total += fabsf(1.0f - d.y * inv_n);
            total += fabsf(1.0f - d.z * inv_n);
            total += fabsf(1.0f - d.w * inv_n);
        }
        atomicAdd(out, total);
    }
}

extern "C" void kernel_launch(void* const* d_in, const int* in_sizes, int n_in,
                              void* d_out, int out_size)
{
    const float4* Y = (const float4*)d_in[0];
    float* out = (float*)d_out;

    colsq_kernel<<<GRID1, COLS4>>>(Y, out);
    reduce_kernel<<<64, 1024>>>(out);
}